// round 7
// baseline (speedup 1.0000x reference)
#include <cuda_runtime.h>
#include <cuda_bf16.h>
#include <cstdint>

// Problem constants
#define B_   32
#define C_   96
#define HID_ 576
#define H_   28
#define W_   28
#define P_   784
#define NP_  25088

// ---------------- device scratch ----------------
__device__ __align__(16) int8_t g_qxt[NP_ * C_];              // [pix][96] int8
__device__ __align__(16) int8_t g_q1p[HID_ * B_ * 30 * 32];   // planar halo layout
__device__ __align__(16) int8_t g_q2 [NP_ * HID_];            // [pix][576] int8
__device__ __align__(16) int8_t g_qw1[HID_ * C_];             // [co][96]
__device__ __align__(16) int8_t g_qw3[C_ * HID_];             // [co][576]
__device__ __align__(16) int    g_qw2r[HID_ * 4];
__device__ __align__(16) float  g_A1[HID_], g_B1[HID_];
__device__ __align__(16) float  g_A2[HID_], g_B2[HID_];
__device__ __align__(16) float  g_A3[C_],   g_B3[C_];
__device__ float g_c[4];   // [0]=1/ax2 [1]=min(6/ax2,7) [2]=1/ax3 [3]=min(6/ax3,7)

// ---------------- helpers ----------------
__device__ __forceinline__ void mma8(int* c, int a0, int a1, int a2, int a3,
                                     int b0, int b1) {
    asm volatile("mma.sync.aligned.m16n8k32.row.col.s32.s8.s8.s32 "
        "{%0,%1,%2,%3}, {%4,%5,%6,%7}, {%8,%9}, {%0,%1,%2,%3};"
        : "+r"(c[0]), "+r"(c[1]), "+r"(c[2]), "+r"(c[3])
        : "r"(a0), "r"(a1), "r"(a2), "r"(a3), "r"(b0), "r"(b1));
}
__device__ __forceinline__ uint32_t smem_u32(const void* p) {
    uint32_t a;
    asm("{ .reg .u64 t; cvta.to.shared.u64 t, %1; cvt.u32.u64 %0, t; }" : "=r"(a) : "l"(p));
    return a;
}
__device__ __forceinline__ void cpa16(uint32_t s, const void* g) {
    asm volatile("cp.async.cg.shared.global [%0], [%1], 16;" :: "r"(s), "l"(g));
}
#define CPCOMMIT() asm volatile("cp.async.commit_group;" ::: "memory")
#define CPWAIT0()  asm volatile("cp.async.wait_group 0;" ::: "memory")

__device__ __forceinline__ int dp4(int4 a, int4 b, int acc) {
    acc = __dp4a(a.x, b.x, acc);
    acc = __dp4a(a.y, b.y, acc);
    acc = __dp4a(a.z, b.z, acc);
    acc = __dp4a(a.w, b.w, acc);
    return acc;
}
__device__ __forceinline__ int dpw(int lo, int hi, int sel, int w, int acc) {
    return __dp4a((int)__byte_perm((unsigned)lo, (unsigned)hi, (unsigned)sel), w, acc);
}
__device__ __forceinline__ int bnq(int acc, float A, float Bv, float inv, float cm) {
    float f = fmaf((float)acc, A, Bv);
    f = fmaxf(f, 0.0f) * inv;
    f = fminf(f, cm);
    return (int)rintf(f);
}

// ---------------- kernel: setup ----------------
__global__ void k_setup(const float* w1, const float* w2, const float* w3,
                        const float* aw1, const float* ax1,
                        const float* g1, const float* b1, const float* m1, const float* v1,
                        const float* aw2, const float* ax2,
                        const float* g2, const float* b2, const float* m2, const float* v2,
                        const float* aw3, const float* ax3,
                        const float* g3, const float* b3, const float* m3, const float* v3)
{
    int tid = blockIdx.x * blockDim.x + threadIdx.x;
    int nt  = gridDim.x * blockDim.x;
    float a1 = aw1[0], a2 = aw2[0], a3 = aw3[0];

    for (int i = tid; i < HID_ * C_; i += nt)
        g_qw1[i] = (int8_t)(int)rintf(fminf(fmaxf(w1[i] / a1, -8.0f), 7.0f));
    for (int i = tid; i < C_ * HID_; i += nt)
        g_qw3[i] = (int8_t)(int)rintf(fminf(fmaxf(w3[i] / a3, -8.0f), 7.0f));
    for (int c = tid; c < HID_; c += nt) {
        int q[9];
#pragma unroll
        for (int tp = 0; tp < 9; tp++)
            q[tp] = (int)rintf(fminf(fmaxf(w2[c * 9 + tp] / a2, -8.0f), 7.0f));
#pragma unroll
        for (int r = 0; r < 3; r++)
            g_qw2r[c * 4 + r] = (q[3*r] & 255) | ((q[3*r+1] & 255) << 8) | ((q[3*r+2] & 255) << 16);
        float s1 = g1[c] / sqrtf(v1[c] + 1e-5f);
        g_A1[c] = ax1[0] * a1 * s1;
        g_B1[c] = b1[c] - m1[c] * s1;
        float s2 = g2[c] / sqrtf(v2[c] + 1e-5f);
        g_A2[c] = ax2[0] * a2 * s2;
        g_B2[c] = b2[c] - m2[c] * s2;
    }
    for (int c = tid; c < C_; c += nt) {
        float s3 = g3[c] / sqrtf(v3[c] + 1e-5f);
        g_A3[c] = ax3[0] * a3 * s3;
        g_B3[c] = b3[c] - m3[c] * s3;
    }
    if (tid == 0) {
        g_c[0] = 1.0f / ax2[0];
        g_c[1] = fminf(6.0f / ax2[0], 7.0f);
        g_c[2] = 1.0f / ax3[0];
        g_c[3] = fminf(6.0f / ax3[0], 7.0f);
    }
}

// ---------------- kernel: halo-only zero of g_q1p ----------------
__global__ void k_zero()
{
    int pid = blockIdx.x * 256 + threadIdx.x;
    if (pid >= HID_ * B_) return;
    int4* p4 = reinterpret_cast<int4*>(g_q1p + (size_t)pid * 960);
    int4 z = make_int4(0, 0, 0, 0);
    p4[0] = z; p4[1] = z;
    p4[58] = z; p4[59] = z;
    int* pi = reinterpret_cast<int*>(g_q1p + (size_t)pid * 960);
#pragma unroll
    for (int r = 1; r < 29; r++) pi[r * 8 + 7] = 0;
}

// ---------------- kernel: quantize + transpose x ----------------
__global__ void k_quantx(const float* __restrict__ x, const float* __restrict__ ax1)
{
    __shared__ int8_t sq[C_ * 36];
    int t  = threadIdx.x;
    int n  = blockIdx.x / 25;
    int p0 = (blockIdx.x % 25) * 32;
    float a = ax1[0];

#pragma unroll
    for (int r = 0; r < 12; r++) {
        int idx = t + r * 256;
        int c = idx >> 5, j = idx & 31;
        int p = p0 + j;
        float val = (p < P_) ? x[(n * C_ + c) * P_ + p] : 0.0f;
        float q = rintf(fminf(fmaxf(val / a, -8.0f), 7.0f));
        sq[c * 36 + j] = (int8_t)(int)q;
    }
    __syncthreads();
#pragma unroll
    for (int r = 0; r < 3; r++) {
        int idx = t + r * 256;
        int j = idx / 24, ii = idx % 24;
        int p = p0 + j;
        if (p < P_) {
            int b0 = (int)sq[(ii * 4 + 0) * 36 + j] & 255;
            int b1 = (int)sq[(ii * 4 + 1) * 36 + j] & 255;
            int b2 = (int)sq[(ii * 4 + 2) * 36 + j] & 255;
            int b3 = (int)sq[(ii * 4 + 3) * 36 + j] & 255;
            reinterpret_cast<int*>(g_qxt)[(n * P_ + p) * 24 + ii] =
                b0 | (b1 << 8) | (b2 << 16) | (b3 << 24);
        }
    }
}

// ---------------- kernel: conv1 hybrid mma+dp4a (112 pix x 144 co, K=96) ----------------
// 448 threads / 14 warps. mma: co 0..79 (warp = pixgroup w>>1, nb-half w&1, 5 nb).
// dp4a: co 80..143, thread = 4co x 4pix cell.
__global__ __launch_bounds__(448, 2) void k_conv1m()
{
    __shared__ __align__(16) char smc[28672 + 1216];
    int* sA = reinterpret_cast<int*>(smc);               // [112][28]
    int* sW = reinterpret_cast<int*>(smc + 12544);       // [144][28]
    int8_t* sS = reinterpret_cast<int8_t*>(smc);         // overlay after compute: [144][116]
    float* sAf = reinterpret_cast<float*>(smc + 28672);  // 144
    float* sBf = sAf + 144;

    int t = threadIdx.x, w = t >> 5, lane = t & 31;
    int q = lane >> 2, rr = lane & 3;
    int pix0 = blockIdx.x * 112;
    int co0  = blockIdx.y * 144;

    // load A: 672 int4
    {
        const int4* gA = reinterpret_cast<const int4*>(g_qxt + (size_t)pix0 * 96);
#pragma unroll
        for (int it = 0; it < 2; it++) {
            int i = t + it * 448;
            if (i < 672) {
                int r = i / 6, c = i % 6;
                *reinterpret_cast<int4*>(&sA[r * 28 + c * 4]) = gA[i];
            }
        }
    }
    // load W: 864 int4
    {
        const int4* gW = reinterpret_cast<const int4*>(g_qw1 + (size_t)co0 * 96);
#pragma unroll
        for (int it = 0; it < 2; it++) {
            int i = t + it * 448;
            if (i < 864) {
                int r = i / 6, c = i % 6;
                *reinterpret_cast<int4*>(&sW[r * 28 + c * 4]) = gW[i];
            }
        }
    }
    if (t < 144) { sAf[t] = g_A1[co0 + t]; sBf[t] = g_B1[co0 + t]; }
    __syncthreads();

    float inv = g_c[0], cm = g_c[1];

    // ---- mma part: co 0..79, 5 n-blocks per warp ----
    int acc[5][4];
#pragma unroll
    for (int nb = 0; nb < 5; nb++)
#pragma unroll
        for (int j = 0; j < 4; j++) acc[nb][j] = 0;

    int nb0 = (w & 1) * 5;
    const int* ap = &sA[((w >> 1) * 16 + q) * 28 + rr];
#pragma unroll
    for (int k = 0; k < 3; k++) {
        int a0 = ap[k * 8];
        int a1 = ap[k * 8 + 8 * 28];
        int a2 = ap[k * 8 + 4];
        int a3 = ap[k * 8 + 8 * 28 + 4];
#pragma unroll
        for (int nb = 0; nb < 5; nb++) {
            const int* bp = &sW[((nb0 + nb) * 8 + q) * 28 + rr + k * 8];
            mma8(acc[nb], a0, a1, a2, a3, bp[0], bp[4]);
        }
    }
    // quantize + pack mma results (frees acc registers before dp4a phase)
    int pk[5];
#pragma unroll
    for (int nb = 0; nb < 5; nb++) {
        int ca = (nb0 + nb) * 8 + rr * 2, cb = ca + 1;
        int q0 = bnq(acc[nb][0], sAf[ca], sBf[ca], inv, cm);
        int q1 = bnq(acc[nb][1], sAf[cb], sBf[cb], inv, cm);
        int q2 = bnq(acc[nb][2], sAf[ca], sBf[ca], inv, cm);
        int q3 = bnq(acc[nb][3], sAf[cb], sBf[cb], inv, cm);
        pk[nb] = (q0 & 255) | ((q1 & 255) << 8) | ((q2 & 255) << 16) | ((q3 & 255) << 24);
    }

    // ---- dp4a part: co 80..143, thread = 4co x 4pix ----
    int cg = t / 28, pg = t % 28;
    int acc2[4][4];
#pragma unroll
    for (int i = 0; i < 4; i++)
#pragma unroll
        for (int j = 0; j < 4; j++) acc2[i][j] = 0;
#pragma unroll
    for (int g = 0; g < 6; g++) {
        int4 wv[4], xv[4];
#pragma unroll
        for (int i = 0; i < 4; i++)
            wv[i] = *reinterpret_cast<const int4*>(&sW[(80 + cg * 4 + i) * 28 + g * 4]);
#pragma unroll
        for (int j = 0; j < 4; j++)
            xv[j] = *reinterpret_cast<const int4*>(&sA[(pg * 4 + j) * 28 + g * 4]);
#pragma unroll
        for (int i = 0; i < 4; i++)
#pragma unroll
            for (int j = 0; j < 4; j++)
                acc2[i][j] = dp4(wv[i], xv[j], acc2[i][j]);
    }
    __syncthreads();   // all reads of sA/sW done before overlay

    // stage mma results [co][pix]
    int pr0 = (w >> 1) * 16 + q, pr1 = pr0 + 8;
#pragma unroll
    for (int nb = 0; nb < 5; nb++) {
        int ca = (nb0 + nb) * 8 + rr * 2, cb = ca + 1;
        sS[ca * 116 + pr0] = (int8_t)(pk[nb] & 255);
        sS[cb * 116 + pr0] = (int8_t)((pk[nb] >> 8) & 255);
        sS[ca * 116 + pr1] = (int8_t)((pk[nb] >> 16) & 255);
        sS[cb * 116 + pr1] = (int8_t)((pk[nb] >> 24) & 255);
    }
    // stage dp4a results
#pragma unroll
    for (int i = 0; i < 4; i++) {
        int co = 80 + cg * 4 + i;
        char4 c4 = make_char4(
            (char)bnq(acc2[i][0], sAf[co], sBf[co], inv, cm),
            (char)bnq(acc2[i][1], sAf[co], sBf[co], inv, cm),
            (char)bnq(acc2[i][2], sAf[co], sBf[co], inv, cm),
            (char)bnq(acc2[i][3], sAf[co], sBf[co], inv, cm));
        *reinterpret_cast<char4*>(&sS[co * 116 + pg * 4]) = c4;
    }
    __syncthreads();

    // coalesced copy to planar: 144 co x 4 rows x 7 ints = 4032 ints
    int n = pix0 / P_;
    int yy = (pix0 % P_) / W_;
#pragma unroll
    for (int it = 0; it < 9; it++) {
        int i = t + it * 448;
        int co = i / 28, rem = i % 28, seg = rem / 7, wd = rem % 7;
        int val = *reinterpret_cast<const int*>(&sS[co * 116 + seg * 28 + wd * 4]);
        *reinterpret_cast<int*>(
            &g_q1p[(size_t)(co0 + co) * 30720 + n * 960 + (yy + seg + 1) * 32 + wd * 4]) = val;
    }
}

// ---------------- kernel: depthwise 3x3 + bn2 + relu6 + quant ----------------
__global__ __launch_bounds__(288) void k_dw()
{
    __shared__ __align__(16) int s_in[72 * 52];
    __shared__ __align__(16) int s_out[2016];
    int t  = threadIdx.x;
    int b  = blockIdx.x;
    int cg = b & 7;
    int s  = (b >> 3) % 7;
    int n  = b / 56;
    int c0 = cg * 72;

    const int4* g4 = reinterpret_cast<const int4*>(g_q1p);
    int4* s4 = reinterpret_cast<int4*>(s_in);
#pragma unroll
    for (int it = 0; it < 3; it++) {
        int idx = t + it * 288;
        int c = idx / 12, r4 = idx % 12;
        s4[c * 13 + r4] = g4[((c0 + c) * 32 + n) * 60 + s * 8 + r4];
    }
    __syncthreads();

    int c = t % 72, y = t / 72;
    int gc = c0 + c;
    int w0 = g_qw2r[gc * 4 + 0];
    int w1 = g_qw2r[gc * 4 + 1];
    int w2 = g_qw2r[gc * 4 + 2];
    float A = g_A2[gc], Bv = g_B2[gc];
    float inv = g_c[2], cm = g_c[3];

    const int4* sb = s4 + c * 13 + y * 2;
    int4 t0 = sb[0], t1 = sb[1], t2 = sb[2], t3 = sb[3], t4 = sb[4], t5 = sb[5];
    int r0[8] = {t0.x, t0.y, t0.z, t0.w, t1.x, t1.y, t1.z, t1.w};
    int r1[8] = {t2.x, t2.y, t2.z, t2.w, t3.x, t3.y, t3.z, t3.w};
    int r2[8] = {t4.x, t4.y, t4.z, t4.w, t5.x, t5.y, t5.z, t5.w};

    int8_t* so = reinterpret_cast<int8_t*>(s_out);
#pragma unroll
    for (int j = 0; j < 7; j++) {
        int p0 = j ? r0[j - 1] : 0, m0 = r0[j], q0 = r0[j + 1];
        int p1 = j ? r1[j - 1] : 0, m1 = r1[j], q1 = r1[j + 1];
        int p2 = j ? r2[j - 1] : 0, m2 = r2[j], q2 = r2[j + 1];
        int a0 = 0, a1 = 0, a2 = 0, a3 = 0;
        a0 = dpw(p0, m0, 0x5543, w0, a0);
        a1 = dpw(p0, m0, 0x6654, w0, a1);
        a2 = dpw(p0, m0, 0x7765, w0, a2);
        a3 = dpw(m0, q0, 0x4432, w0, a3);
        a0 = dpw(p1, m1, 0x5543, w1, a0);
        a1 = dpw(p1, m1, 0x6654, w1, a1);
        a2 = dpw(p1, m1, 0x7765, w1, a2);
        a3 = dpw(m1, q1, 0x4432, w1, a3);
        a0 = dpw(p2, m2, 0x5543, w2, a0);
        a1 = dpw(p2, m2, 0x6654, w2, a1);
        a2 = dpw(p2, m2, 0x7765, w2, a2);
        a3 = dpw(m2, q2, 0x4432, w2, a3);

        int pixb = (y * 28 + j * 4) * 72 + c;
        so[pixb      ] = (int8_t)bnq(a0, A, Bv, inv, cm);
        so[pixb + 72 ] = (int8_t)bnq(a1, A, Bv, inv, cm);
        so[pixb + 144] = (int8_t)bnq(a2, A, Bv, inv, cm);
        so[pixb + 216] = (int8_t)bnq(a3, A, Bv, inv, cm);
    }
    __syncthreads();

    int pbase = n * P_ + s * 112;
    int* gq2 = reinterpret_cast<int*>(g_q2);
#pragma unroll
    for (int it = 0; it < 7; it++) {
        int idx = t + it * 288;
        int pix = idx / 18, k = idx % 18;
        gq2[(pbase + pix) * 144 + cg * 18 + k] = s_out[idx];
    }
}

// ---------------- kernel: conv3 hybrid mma+dp4a + cp.async double buffer ----------------
// 112 pix x 48 co, K=576 in 3 chunks. mma: co 0..31 (4 nb/warp). dp4a: co 32..47 (2co x 4pix/thread).
#define C3A(buf) ((buf) * 5824)
#define C3W(buf) (11648 + (buf) * 2496)
#define C3_SMEM (66560 + 384)

__global__ __launch_bounds__(224) void k_conv3m(const float* __restrict__ x,
                                                float* __restrict__ out)
{
    extern __shared__ __align__(16) int sU[];
    uint32_t sb = smem_u32(sU);
    float* sAf = reinterpret_cast<float*>(sU + 16640);
    float* sBf = sAf + 48;
    float* stg = reinterpret_cast<float*>(sU);   // overlay after final compute

    int t = threadIdx.x, w = t >> 5, lane = t & 31;
    int q = lane >> 2, rr = lane & 3;
    int pix0 = blockIdx.x * 112;
    int co0  = blockIdx.y * 48;
    int cg = t / 28, pg = t % 28;

    if (t < 48) { sAf[t] = g_A3[co0 + t]; sBf[t] = g_B3[co0 + t]; }

    auto load_chunk = [&](int buf, int ch) {
        uint32_t ab = sb + C3A(buf) * 4;
        uint32_t wb = sb + C3W(buf) * 4;
#pragma unroll
        for (int it = 0; it < 6; it++) {
            int i = t + it * 224;
            int r = i / 12, c = i % 12;
            cpa16(ab + (uint32_t)(r * 52 + c * 4) * 4,
                  g_q2 + (size_t)(pix0 + r) * HID_ + ch * 192 + c * 16);
        }
#pragma unroll
        for (int it = 0; it < 3; it++) {
            int i = t + it * 224;
            if (i < 576) {
                int r = i / 12, c = i % 12;
                cpa16(wb + (uint32_t)(r * 52 + c * 4) * 4,
                      g_qw3 + (size_t)(co0 + r) * HID_ + ch * 192 + c * 16);
            }
        }
    };

    load_chunk(0, 0);
    CPCOMMIT();
    CPWAIT0();
    __syncthreads();

    int acc[4][4];     // mma co 0..31
    int acc2[2][4];    // dp4a co 32..47
#pragma unroll
    for (int nb = 0; nb < 4; nb++)
#pragma unroll
        for (int j = 0; j < 4; j++) acc[nb][j] = 0;
#pragma unroll
    for (int i = 0; i < 2; i++)
#pragma unroll
        for (int j = 0; j < 4; j++) acc2[i][j] = 0;

#pragma unroll
    for (int ch = 0; ch < 3; ch++) {
        if (ch < 2) { load_chunk((ch + 1) & 1, ch + 1); CPCOMMIT(); }

        const int* sA = sU + C3A(ch & 1);
        const int* sW = sU + C3W(ch & 1);

        // mma: 4 n-blocks x 6 k-steps
        const int* ap = &sA[(w * 16 + q) * 52 + rr];
#pragma unroll
        for (int k = 0; k < 6; k++) {
            int a0 = ap[k * 8];
            int a1 = ap[k * 8 + 8 * 52];
            int a2 = ap[k * 8 + 4];
            int a3 = ap[k * 8 + 8 * 52 + 4];
#pragma unroll
            for (int nb = 0; nb < 4; nb++) {
                const int* bp = &sW[(nb * 8 + q) * 52 + rr + k * 8];
                mma8(acc[nb], a0, a1, a2, a3, bp[0], bp[4]);
            }
        }
        // dp4a: co 32..47
#pragma unroll
        for (int g = 0; g < 12; g++) {
            int4 wv0 = *reinterpret_cast<const int4*>(&sW[(32 + cg * 2) * 52 + g * 4]);
            int4 wv1 = *reinterpret_cast<const int4*>(&sW[(32 + cg * 2 + 1) * 52 + g * 4]);
#pragma unroll
            for (int j = 0; j < 4; j++) {
                int4 xv = *reinterpret_cast<const int4*>(&sA[(pg * 4 + j) * 52 + g * 4]);
                acc2[0][j] = dp4(wv0, xv, acc2[0][j]);
                acc2[1][j] = dp4(wv1, xv, acc2[1][j]);
            }
        }
        if (ch < 2) { CPWAIT0(); __syncthreads(); }
    }
    __syncthreads();   // all compute done before stage overlay

    // stage fp32 [co][pix] stride 113
    int pr0 = w * 16 + q, pr1 = pr0 + 8;
#pragma unroll
    for (int nb = 0; nb < 4; nb++) {
        int ca = nb * 8 + rr * 2, cb = ca + 1;
        stg[ca * 113 + pr0] = (float)acc[nb][0];
        stg[cb * 113 + pr0] = (float)acc[nb][1];
        stg[ca * 113 + pr1] = (float)acc[nb][2];
        stg[cb * 113 + pr1] = (float)acc[nb][3];
    }
#pragma unroll
    for (int i = 0; i < 2; i++) {
        int co = 32 + cg * 2 + i;
#pragma unroll
        for (int j = 0; j < 4; j++)
            stg[co * 113 + pg * 4 + j] = (float)acc2[i][j];
    }
    __syncthreads();

    int n = pix0 / P_;
    int prow = pix0 % P_;
#pragma unroll
    for (int it = 0; it < 24; it++) {
        int i = t + it * 224;
        int co = i / 112, p = i % 112;
        int off = (n * C_ + co0 + co) * P_ + prow + p;
        out[off] = x[off] + fmaf(stg[co * 113 + p], sAf[co], sBf[co]);
    }
}

// ---------------- launch ----------------
extern "C" void kernel_launch(void* const* d_in, const int* in_sizes, int n_in,
                              void* d_out, int out_size)
{
    const float* x   = (const float*)d_in[0];
    const float* w1  = (const float*)d_in[1];
    const float* w2  = (const float*)d_in[2];
    const float* w3  = (const float*)d_in[3];
    const float* aw1 = (const float*)d_in[4];
    const float* ax1 = (const float*)d_in[5];
    const float* g1  = (const float*)d_in[6];
    const float* b1  = (const float*)d_in[7];
    const float* m1  = (const float*)d_in[8];
    const float* v1  = (const float*)d_in[9];
    const float* aw2 = (const float*)d_in[10];
    const float* ax2 = (const float*)d_in[11];
    const float* g2  = (const float*)d_in[12];
    const float* b2  = (const float*)d_in[13];
    const float* m2  = (const float*)d_in[14];
    const float* v2  = (const float*)d_in[15];
    const float* aw3 = (const float*)d_in[16];
    const float* ax3 = (const float*)d_in[17];
    const float* g3  = (const float*)d_in[18];
    const float* b3  = (const float*)d_in[19];
    const float* m3  = (const float*)d_in[20];
    const float* v3  = (const float*)d_in[21];
    float* out = (float*)d_out;

    cudaFuncSetAttribute(k_conv3m, cudaFuncAttributeMaxDynamicSharedMemorySize, C3_SMEM);

    k_setup<<<32, 256>>>(w1, w2, w3, aw1, ax1, g1, b1, m1, v1,
                         aw2, ax2, g2, b2, m2, v2, aw3, ax3, g3, b3, m3, v3);
    k_zero<<<72, 256>>>();
    k_quantx<<<B_ * 25, 256>>>(x, ax1);
    k_conv1m<<<dim3(NP_ / 112, 4), 448>>>();
    k_dw<<<1792, 288>>>();
    k_conv3m<<<dim3(NP_ / 112, 2), 224, C3_SMEM>>>(x, out);
}

// round 8
// speedup vs baseline: 1.1737x; 1.1737x over previous
#include <cuda_runtime.h>
#include <cuda_bf16.h>
#include <cstdint>

// Problem constants
#define B_   32
#define C_   96
#define HID_ 576
#define H_   28
#define W_   28
#define P_   784
#define NP_  25088

// ---------------- device scratch ----------------
__device__ __align__(16) int8_t g_q1p[HID_ * B_ * 30 * 32];   // planar halo layout
__device__ __align__(16) int8_t g_q2 [NP_ * HID_];            // [pix][576] int8
__device__ __align__(16) int8_t g_qw1[HID_ * C_];             // [co][96]
__device__ __align__(16) int8_t g_qw3[C_ * HID_];             // [co][576]
__device__ __align__(16) int    g_qw2r[HID_ * 4];
__device__ __align__(16) float  g_A1[HID_], g_B1[HID_];
__device__ __align__(16) float  g_A2[HID_], g_B2[HID_];
__device__ __align__(16) float  g_A3[C_],   g_B3[C_];
__device__ float g_c[4];   // [0]=1/ax2 [1]=min(6/ax2,7) [2]=1/ax3 [3]=min(6/ax3,7)

// ---------------- helpers ----------------
__device__ __forceinline__ void mma8(int* c, int a0, int a1, int a2, int a3,
                                     int b0, int b1) {
    asm volatile("mma.sync.aligned.m16n8k32.row.col.s32.s8.s8.s32 "
        "{%0,%1,%2,%3}, {%4,%5,%6,%7}, {%8,%9}, {%0,%1,%2,%3};"
        : "+r"(c[0]), "+r"(c[1]), "+r"(c[2]), "+r"(c[3])
        : "r"(a0), "r"(a1), "r"(a2), "r"(a3), "r"(b0), "r"(b1));
}
__device__ __forceinline__ uint32_t smem_u32(const void* p) {
    uint32_t a;
    asm("{ .reg .u64 t; cvta.to.shared.u64 t, %1; cvt.u32.u64 %0, t; }" : "=r"(a) : "l"(p));
    return a;
}
__device__ __forceinline__ void cpa16(uint32_t s, const void* g) {
    asm volatile("cp.async.cg.shared.global [%0], [%1], 16;" :: "r"(s), "l"(g));
}
#define CPCOMMIT() asm volatile("cp.async.commit_group;" ::: "memory")
#define CPWAIT0()  asm volatile("cp.async.wait_group 0;" ::: "memory")

__device__ __forceinline__ int dpw(int lo, int hi, int sel, int w, int acc) {
    return __dp4a((int)__byte_perm((unsigned)lo, (unsigned)hi, (unsigned)sel), w, acc);
}
__device__ __forceinline__ int bnq(int acc, float A, float Bv, float inv, float cm) {
    float f = fmaf((float)acc, A, Bv);
    f = fmaxf(f, 0.0f) * inv;
    f = fminf(f, cm);
    return (int)rintf(f);
}

// ---------------- kernel: setup (weights, BN fold) + halo zero of g_q1p ----------------
__global__ void k_setup(const float* w1, const float* w2, const float* w3,
                        const float* aw1, const float* ax1,
                        const float* g1, const float* b1, const float* m1, const float* v1,
                        const float* aw2, const float* ax2,
                        const float* g2, const float* b2, const float* m2, const float* v2,
                        const float* aw3, const float* ax3,
                        const float* g3, const float* b3, const float* m3, const float* v3)
{
    int tid = blockIdx.x * blockDim.x + threadIdx.x;
    int nt  = gridDim.x * blockDim.x;          // 18432
    float a1 = aw1[0], a2 = aw2[0], a3 = aw3[0];

    // halo zero: one thread per (c, n) plane
    if (tid < HID_ * B_) {
        int4* p4 = reinterpret_cast<int4*>(g_q1p + (size_t)tid * 960);
        int4 z = make_int4(0, 0, 0, 0);
        p4[0] = z; p4[1] = z;         // row 0
        p4[58] = z; p4[59] = z;       // row 29
        int* pi = reinterpret_cast<int*>(g_q1p + (size_t)tid * 960);
#pragma unroll
        for (int r = 1; r < 29; r++) pi[r * 8 + 7] = 0;   // x = 28..31
    }

    for (int i = tid; i < HID_ * C_; i += nt)
        g_qw1[i] = (int8_t)(int)rintf(fminf(fmaxf(w1[i] / a1, -8.0f), 7.0f));
    for (int i = tid; i < C_ * HID_; i += nt)
        g_qw3[i] = (int8_t)(int)rintf(fminf(fmaxf(w3[i] / a3, -8.0f), 7.0f));
    for (int c = tid; c < HID_; c += nt) {
        int q[9];
#pragma unroll
        for (int tp = 0; tp < 9; tp++)
            q[tp] = (int)rintf(fminf(fmaxf(w2[c * 9 + tp] / a2, -8.0f), 7.0f));
#pragma unroll
        for (int r = 0; r < 3; r++)
            g_qw2r[c * 4 + r] = (q[3*r] & 255) | ((q[3*r+1] & 255) << 8) | ((q[3*r+2] & 255) << 16);
        float s1 = g1[c] / sqrtf(v1[c] + 1e-5f);
        g_A1[c] = ax1[0] * a1 * s1;
        g_B1[c] = b1[c] - m1[c] * s1;
        float s2 = g2[c] / sqrtf(v2[c] + 1e-5f);
        g_A2[c] = ax2[0] * a2 * s2;
        g_B2[c] = b2[c] - m2[c] * s2;
    }
    for (int c = tid; c < C_; c += nt) {
        float s3 = g3[c] / sqrtf(v3[c] + 1e-5f);
        g_A3[c] = ax3[0] * a3 * s3;
        g_B3[c] = b3[c] - m3[c] * s3;
    }
    if (tid == 0) {
        g_c[0] = 1.0f / ax2[0];
        g_c[1] = fminf(6.0f / ax2[0], 7.0f);
        g_c[2] = 1.0f / ax3[0];
        g_c[3] = fminf(6.0f / ax3[0], 7.0f);
    }
}

// ---------------- kernel: conv1 mma with fused x quantization ----------------
// 112 contiguous pixels (4 rows of one image) x 144 co, K=96.
// 448 threads / 14 warps: warp = (pixgroup w>>1, co-half w&1), 9 n-blocks each.
__global__ __launch_bounds__(448, 2) void k_conv1q(const float* __restrict__ x,
                                                   const float* __restrict__ ax1)
{
    __shared__ __align__(16) char smc[28672 + 1216];
    int* sA = reinterpret_cast<int*>(smc);               // [112][28] ints (112B rows, 96 used)
    int* sW = reinterpret_cast<int*>(smc + 12544);       // [144][28]
    int8_t* sS = reinterpret_cast<int8_t*>(smc);         // overlay after mma: [144][116]
    float* sAf = reinterpret_cast<float*>(smc + 28672);  // 144
    float* sBf = sAf + 144;

    int t = threadIdx.x, w = t >> 5, lane = t & 31;
    int q = lane >> 2, rr = lane & 3;
    int pix0 = blockIdx.x * 112;
    int co0  = blockIdx.y * 144;
    int n    = pix0 / P_;
    int prow = pix0 - n * P_;           // multiple of 112, within one image

    // fused quantize+transpose of x into sA (bytes [px][c])
    {
        float a = __ldg(ax1);
        int8_t* sAb = reinterpret_cast<int8_t*>(smc);
        const float* xb = x + (size_t)n * C_ * P_ + prow;
#pragma unroll
        for (int it = 0; it < 24; it++) {
            int i = t + it * 448;               // 10752 = 96c * 112px
            int c = i / 112, px = i % 112;
            float val = xb[c * P_ + px];
            float qv = rintf(fminf(fmaxf(val / a, -8.0f), 7.0f));
            sAb[px * 112 + c] = (int8_t)(int)qv;
        }
    }
    // load W: 864 int4
    {
        const int4* gW = reinterpret_cast<const int4*>(g_qw1 + (size_t)co0 * 96);
#pragma unroll
        for (int it = 0; it < 2; it++) {
            int i = t + it * 448;
            if (i < 864) {
                int r = i / 6, c = i % 6;
                *reinterpret_cast<int4*>(&sW[r * 28 + c * 4]) = gW[i];
            }
        }
    }
    if (t < 144) { sAf[t] = g_A1[co0 + t]; sBf[t] = g_B1[co0 + t]; }
    __syncthreads();

    int acc[9][4];
#pragma unroll
    for (int nb = 0; nb < 9; nb++)
#pragma unroll
        for (int j = 0; j < 4; j++) acc[nb][j] = 0;

    int hb = (w & 1) * 72;
    const int* ap = &sA[((w >> 1) * 16 + q) * 28 + rr];
#pragma unroll
    for (int k = 0; k < 3; k++) {
        int a0 = ap[k * 8];
        int a1 = ap[k * 8 + 8 * 28];
        int a2 = ap[k * 8 + 4];
        int a3 = ap[k * 8 + 8 * 28 + 4];
#pragma unroll
        for (int nb = 0; nb < 9; nb++) {
            const int* bp = &sW[(hb + nb * 8 + q) * 28 + rr + k * 8];
            mma8(acc[nb], a0, a1, a2, a3, bp[0], bp[4]);
        }
    }
    __syncthreads();   // all warps done reading sA/sW before overlay

    // stage quantized bytes [co][pix]
    float inv = g_c[0], cm = g_c[1];
    int pr0 = (w >> 1) * 16 + q, pr1 = pr0 + 8;
#pragma unroll
    for (int nb = 0; nb < 9; nb++) {
        int ca = hb + nb * 8 + rr * 2, cb = ca + 1;
        sS[ca * 116 + pr0] = (int8_t)bnq(acc[nb][0], sAf[ca], sBf[ca], inv, cm);
        sS[cb * 116 + pr0] = (int8_t)bnq(acc[nb][1], sAf[cb], sBf[cb], inv, cm);
        sS[ca * 116 + pr1] = (int8_t)bnq(acc[nb][2], sAf[ca], sBf[ca], inv, cm);
        sS[cb * 116 + pr1] = (int8_t)bnq(acc[nb][3], sAf[cb], sBf[cb], inv, cm);
    }
    __syncthreads();

    // coalesced copy to planar: 144 co x 4 rows x 7 ints = 4032 ints
    int yy = prow / W_;
#pragma unroll
    for (int it = 0; it < 9; it++) {
        int i = t + it * 448;
        int co = i / 28, rem = i % 28, seg = rem / 7, wd = rem % 7;
        int val = *reinterpret_cast<const int*>(&sS[co * 116 + seg * 28 + wd * 4]);
        *reinterpret_cast<int*>(
            &g_q1p[(size_t)(co0 + co) * 30720 + n * 960 + (yy + seg + 1) * 32 + wd * 4]) = val;
    }
}

// ---------------- kernel: depthwise 3x3 + bn2 + relu6 + quant ----------------
__global__ __launch_bounds__(288) void k_dw()
{
    __shared__ __align__(16) int s_in[72 * 52];
    __shared__ __align__(16) int s_out[2016];
    int t  = threadIdx.x;
    int b  = blockIdx.x;
    int cg = b & 7;
    int s  = (b >> 3) % 7;
    int n  = b / 56;
    int c0 = cg * 72;

    const int4* g4 = reinterpret_cast<const int4*>(g_q1p);
    int4* s4 = reinterpret_cast<int4*>(s_in);
#pragma unroll
    for (int it = 0; it < 3; it++) {
        int idx = t + it * 288;
        int c = idx / 12, r4 = idx % 12;
        s4[c * 13 + r4] = g4[((c0 + c) * 32 + n) * 60 + s * 8 + r4];
    }
    __syncthreads();

    int c = t % 72, y = t / 72;
    int gc = c0 + c;
    int w0 = g_qw2r[gc * 4 + 0];
    int w1 = g_qw2r[gc * 4 + 1];
    int w2 = g_qw2r[gc * 4 + 2];
    float A = g_A2[gc], Bv = g_B2[gc];
    float inv = g_c[2], cm = g_c[3];

    const int4* sb = s4 + c * 13 + y * 2;
    int4 t0 = sb[0], t1 = sb[1], t2 = sb[2], t3 = sb[3], t4 = sb[4], t5 = sb[5];
    int r0[8] = {t0.x, t0.y, t0.z, t0.w, t1.x, t1.y, t1.z, t1.w};
    int r1[8] = {t2.x, t2.y, t2.z, t2.w, t3.x, t3.y, t3.z, t3.w};
    int r2[8] = {t4.x, t4.y, t4.z, t4.w, t5.x, t5.y, t5.z, t5.w};

    int8_t* so = reinterpret_cast<int8_t*>(s_out);
#pragma unroll
    for (int j = 0; j < 7; j++) {
        int p0 = j ? r0[j - 1] : 0, m0 = r0[j], q0 = r0[j + 1];
        int p1 = j ? r1[j - 1] : 0, m1 = r1[j], q1 = r1[j + 1];
        int p2 = j ? r2[j - 1] : 0, m2 = r2[j], q2 = r2[j + 1];
        int a0 = 0, a1 = 0, a2 = 0, a3 = 0;
        a0 = dpw(p0, m0, 0x5543, w0, a0);
        a1 = dpw(p0, m0, 0x6654, w0, a1);
        a2 = dpw(p0, m0, 0x7765, w0, a2);
        a3 = dpw(m0, q0, 0x4432, w0, a3);
        a0 = dpw(p1, m1, 0x5543, w1, a0);
        a1 = dpw(p1, m1, 0x6654, w1, a1);
        a2 = dpw(p1, m1, 0x7765, w1, a2);
        a3 = dpw(m1, q1, 0x4432, w1, a3);
        a0 = dpw(p2, m2, 0x5543, w2, a0);
        a1 = dpw(p2, m2, 0x6654, w2, a1);
        a2 = dpw(p2, m2, 0x7765, w2, a2);
        a3 = dpw(m2, q2, 0x4432, w2, a3);

        int pixb = (y * 28 + j * 4) * 72 + c;
        so[pixb      ] = (int8_t)bnq(a0, A, Bv, inv, cm);
        so[pixb + 72 ] = (int8_t)bnq(a1, A, Bv, inv, cm);
        so[pixb + 144] = (int8_t)bnq(a2, A, Bv, inv, cm);
        so[pixb + 216] = (int8_t)bnq(a3, A, Bv, inv, cm);
    }
    __syncthreads();

    int pbase = n * P_ + s * 112;
    int* gq2 = reinterpret_cast<int*>(g_q2);
#pragma unroll
    for (int it = 0; it < 7; it++) {
        int idx = t + it * 288;
        int pix = idx / 18, k = idx % 18;
        gq2[(pbase + pix) * 144 + cg * 18 + k] = s_out[idx];
    }
}

// ---------------- kernel: conv3 via mma.sync + cp.async double buffer ----------------
// 112 pix x 48 co, K=576 in 3 chunks of 192; 7 warps each m16 x n48.
#define C3A(buf) ((buf) * 5824)
#define C3W(buf) (11648 + (buf) * 2496)
#define C3_SMEM (66560 + 384)

__global__ __launch_bounds__(224) void k_conv3m(const float* __restrict__ x,
                                                float* __restrict__ out)
{
    extern __shared__ __align__(16) int sU[];
    uint32_t sb = smem_u32(sU);
    float* sAf = reinterpret_cast<float*>(sU + 16640);
    float* sBf = sAf + 48;
    float* stg = reinterpret_cast<float*>(sU);   // overlay after final mma

    int t = threadIdx.x, w = t >> 5, lane = t & 31;
    int q = lane >> 2, rr = lane & 3;
    int pix0 = blockIdx.x * 112;
    int co0  = blockIdx.y * 48;

    if (t < 48) { sAf[t] = g_A3[co0 + t]; sBf[t] = g_B3[co0 + t]; }

    auto load_chunk = [&](int buf, int ch) {
        uint32_t ab = sb + C3A(buf) * 4;
        uint32_t wb = sb + C3W(buf) * 4;
#pragma unroll
        for (int it = 0; it < 6; it++) {
            int i = t + it * 224;
            int r = i / 12, c = i % 12;
            cpa16(ab + (uint32_t)(r * 52 + c * 4) * 4,
                  g_q2 + (size_t)(pix0 + r) * HID_ + ch * 192 + c * 16);
        }
#pragma unroll
        for (int it = 0; it < 3; it++) {
            int i = t + it * 224;
            if (i < 576) {
                int r = i / 12, c = i % 12;
                cpa16(wb + (uint32_t)(r * 52 + c * 4) * 4,
                      g_qw3 + (size_t)(co0 + r) * HID_ + ch * 192 + c * 16);
            }
        }
    };

    load_chunk(0, 0);
    CPCOMMIT();
    CPWAIT0();
    __syncthreads();

    int acc[6][4];
#pragma unroll
    for (int nb = 0; nb < 6; nb++)
#pragma unroll
        for (int j = 0; j < 4; j++) acc[nb][j] = 0;

#pragma unroll
    for (int ch = 0; ch < 3; ch++) {
        if (ch < 2) { load_chunk((ch + 1) & 1, ch + 1); CPCOMMIT(); }

        const int* sA = sU + C3A(ch & 1);
        const int* sW = sU + C3W(ch & 1);
        const int* ap = &sA[(w * 16 + q) * 52 + rr];
#pragma unroll
        for (int k = 0; k < 6; k++) {
            int a0 = ap[k * 8];
            int a1 = ap[k * 8 + 8 * 52];
            int a2 = ap[k * 8 + 4];
            int a3 = ap[k * 8 + 8 * 52 + 4];
#pragma unroll
            for (int nb = 0; nb < 6; nb++) {
                const int* bp = &sW[(nb * 8 + q) * 52 + rr + k * 8];
                mma8(acc[nb], a0, a1, a2, a3, bp[0], bp[4]);
            }
        }
        if (ch < 2) { CPWAIT0(); __syncthreads(); }
    }
    __syncthreads();   // all warps done with buf0 before stage overlay

    // stage fp32 [co][pix] stride 113
    int pr0 = w * 16 + q, pr1 = pr0 + 8;
#pragma unroll
    for (int nb = 0; nb < 6; nb++) {
        int ca = nb * 8 + rr * 2, cb = ca + 1;
        stg[ca * 113 + pr0] = (float)acc[nb][0];
        stg[cb * 113 + pr0] = (float)acc[nb][1];
        stg[ca * 113 + pr1] = (float)acc[nb][2];
        stg[cb * 113 + pr1] = (float)acc[nb][3];
    }
    __syncthreads();

    int n = pix0 / P_;
    int prow = pix0 % P_;
#pragma unroll
    for (int it = 0; it < 24; it++) {
        int i = t + it * 224;
        int co = i / 112, p = i % 112;
        int off = (n * C_ + co0 + co) * P_ + prow + p;
        out[off] = x[off] + fmaf(stg[co * 113 + p], sAf[co], sBf[co]);
    }
}

// ---------------- launch ----------------
extern "C" void kernel_launch(void* const* d_in, const int* in_sizes, int n_in,
                              void* d_out, int out_size)
{
    const float* x   = (const float*)d_in[0];
    const float* w1  = (const float*)d_in[1];
    const float* w2  = (const float*)d_in[2];
    const float* w3  = (const float*)d_in[3];
    const float* aw1 = (const float*)d_in[4];
    const float* ax1 = (const float*)d_in[5];
    const float* g1  = (const float*)d_in[6];
    const float* b1  = (const float*)d_in[7];
    const float* m1  = (const float*)d_in[8];
    const float* v1  = (const float*)d_in[9];
    const float* aw2 = (const float*)d_in[10];
    const float* ax2 = (const float*)d_in[11];
    const float* g2  = (const float*)d_in[12];
    const float* b2  = (const float*)d_in[13];
    const float* m2  = (const float*)d_in[14];
    const float* v2  = (const float*)d_in[15];
    const float* aw3 = (const float*)d_in[16];
    const float* ax3 = (const float*)d_in[17];
    const float* g3  = (const float*)d_in[18];
    const float* b3  = (const float*)d_in[19];
    const float* m3  = (const float*)d_in[20];
    const float* v3  = (const float*)d_in[21];
    float* out = (float*)d_out;

    cudaFuncSetAttribute(k_conv3m, cudaFuncAttributeMaxDynamicSharedMemorySize, C3_SMEM);

    k_setup<<<72, 256>>>(w1, w2, w3, aw1, ax1, g1, b1, m1, v1,
                         aw2, ax2, g2, b2, m2, v2, aw3, ax3, g3, b3, m3, v3);
    k_conv1q<<<dim3(NP_ / 112, 4), 448>>>(x, ax1);
    k_dw<<<1792, 288>>>();
    k_conv3m<<<dim3(NP_ / 112, 2), 224, C3_SMEM>>>(x, out);
}

// round 9
// speedup vs baseline: 1.2935x; 1.1021x over previous
#include <cuda_runtime.h>
#include <cuda_bf16.h>
#include <cstdint>

// Problem constants
#define B_   32
#define C_   96
#define HID_ 576
#define H_   28
#define W_   28
#define P_   784
#define NP_  25088

// ---------------- device scratch ----------------
__device__ __align__(16) int8_t g_qxt[NP_ * C_];              // [pix][96] int8
__device__ __align__(16) int8_t g_q1p[HID_ * B_ * 30 * 32];   // planar halo layout
__device__ __align__(16) int8_t g_q2 [NP_ * HID_];            // [pix][576] int8
__device__ __align__(16) int8_t g_qw1[HID_ * C_];             // [co][96]
__device__ __align__(16) int8_t g_qw3[C_ * HID_];             // [co][576]
__device__ __align__(16) int    g_qw2r[HID_ * 4];
__device__ __align__(16) float  g_A1[HID_], g_B1[HID_];
__device__ __align__(16) float  g_A2[HID_], g_B2[HID_];
__device__ __align__(16) float  g_A3[C_],   g_B3[C_];
__device__ float g_c[4];   // [0]=1/ax2 [1]=min(6/ax2,7) [2]=1/ax3 [3]=min(6/ax3,7)

// ---------------- helpers ----------------
__device__ __forceinline__ void mma8(int* c, int a0, int a1, int a2, int a3,
                                     int b0, int b1) {
    asm volatile("mma.sync.aligned.m16n8k32.row.col.s32.s8.s8.s32 "
        "{%0,%1,%2,%3}, {%4,%5,%6,%7}, {%8,%9}, {%0,%1,%2,%3};"
        : "+r"(c[0]), "+r"(c[1]), "+r"(c[2]), "+r"(c[3])
        : "r"(a0), "r"(a1), "r"(a2), "r"(a3), "r"(b0), "r"(b1));
}
__device__ __forceinline__ uint32_t smem_u32(const void* p) {
    uint32_t a;
    asm("{ .reg .u64 t; cvta.to.shared.u64 t, %1; cvt.u32.u64 %0, t; }" : "=r"(a) : "l"(p));
    return a;
}
__device__ __forceinline__ void cpa16(uint32_t s, const void* g) {
    asm volatile("cp.async.cg.shared.global [%0], [%1], 16;" :: "r"(s), "l"(g));
}
#define CPCOMMIT() asm volatile("cp.async.commit_group;" ::: "memory")
#define CPWAIT0()  asm volatile("cp.async.wait_group 0;" ::: "memory")

__device__ __forceinline__ int dpw(int lo, int hi, int sel, int w, int acc) {
    return __dp4a((int)__byte_perm((unsigned)lo, (unsigned)hi, (unsigned)sel), w, acc);
}
__device__ __forceinline__ int bnq(int acc, float A, float Bv, float inv, float cm) {
    float f = fmaf((float)acc, A, Bv);
    f = fmaxf(f, 0.0f) * inv;
    f = fminf(f, cm);
    return (int)rintf(f);
}

// ---------------- kernel: setup (weights, BN fold) + halo zero ----------------
__global__ void k_setup(const float* w1, const float* w2, const float* w3,
                        const float* aw1, const float* ax1,
                        const float* g1, const float* b1, const float* m1, const float* v1,
                        const float* aw2, const float* ax2,
                        const float* g2, const float* b2, const float* m2, const float* v2,
                        const float* aw3, const float* ax3,
                        const float* g3, const float* b3, const float* m3, const float* v3)
{
    int tid = blockIdx.x * blockDim.x + threadIdx.x;
    int nt  = gridDim.x * blockDim.x;          // 18432
    float a1 = aw1[0], a2 = aw2[0], a3 = aw3[0];

    if (tid < HID_ * B_) {
        int4* p4 = reinterpret_cast<int4*>(g_q1p + (size_t)tid * 960);
        int4 z = make_int4(0, 0, 0, 0);
        p4[0] = z; p4[1] = z;
        p4[58] = z; p4[59] = z;
        int* pi = reinterpret_cast<int*>(g_q1p + (size_t)tid * 960);
#pragma unroll
        for (int r = 1; r < 29; r++) pi[r * 8 + 7] = 0;
    }

    for (int i = tid; i < HID_ * C_; i += nt)
        g_qw1[i] = (int8_t)(int)rintf(fminf(fmaxf(w1[i] / a1, -8.0f), 7.0f));
    for (int i = tid; i < C_ * HID_; i += nt)
        g_qw3[i] = (int8_t)(int)rintf(fminf(fmaxf(w3[i] / a3, -8.0f), 7.0f));
    for (int c = tid; c < HID_; c += nt) {
        int q[9];
#pragma unroll
        for (int tp = 0; tp < 9; tp++)
            q[tp] = (int)rintf(fminf(fmaxf(w2[c * 9 + tp] / a2, -8.0f), 7.0f));
#pragma unroll
        for (int r = 0; r < 3; r++)
            g_qw2r[c * 4 + r] = (q[3*r] & 255) | ((q[3*r+1] & 255) << 8) | ((q[3*r+2] & 255) << 16);
        float s1 = g1[c] / sqrtf(v1[c] + 1e-5f);
        g_A1[c] = ax1[0] * a1 * s1;
        g_B1[c] = b1[c] - m1[c] * s1;
        float s2 = g2[c] / sqrtf(v2[c] + 1e-5f);
        g_A2[c] = ax2[0] * a2 * s2;
        g_B2[c] = b2[c] - m2[c] * s2;
    }
    for (int c = tid; c < C_; c += nt) {
        float s3 = g3[c] / sqrtf(v3[c] + 1e-5f);
        g_A3[c] = ax3[0] * a3 * s3;
        g_B3[c] = b3[c] - m3[c] * s3;
    }
    if (tid == 0) {
        g_c[0] = 1.0f / ax2[0];
        g_c[1] = fminf(6.0f / ax2[0], 7.0f);
        g_c[2] = 1.0f / ax3[0];
        g_c[3] = fminf(6.0f / ax3[0], 7.0f);
    }
}

// ---------------- kernel: quantize + transpose x (NCHW fp32 -> [pix][c] int8) ----------------
__global__ void k_quantx(const float* __restrict__ x, const float* __restrict__ ax1)
{
    __shared__ int8_t sq[C_ * 36];
    int t  = threadIdx.x;
    int n  = blockIdx.x / 25;
    int p0 = (blockIdx.x % 25) * 32;
    float a = ax1[0];

#pragma unroll
    for (int r = 0; r < 12; r++) {
        int idx = t + r * 256;
        int c = idx >> 5, j = idx & 31;
        int p = p0 + j;
        float val = (p < P_) ? x[(n * C_ + c) * P_ + p] : 0.0f;
        float q = rintf(fminf(fmaxf(val / a, -8.0f), 7.0f));
        sq[c * 36 + j] = (int8_t)(int)q;
    }
    __syncthreads();
#pragma unroll
    for (int r = 0; r < 3; r++) {
        int idx = t + r * 256;
        int j = idx / 24, ii = idx % 24;
        int p = p0 + j;
        if (p < P_) {
            int b0 = (int)sq[(ii * 4 + 0) * 36 + j] & 255;
            int b1 = (int)sq[(ii * 4 + 1) * 36 + j] & 255;
            int b2 = (int)sq[(ii * 4 + 2) * 36 + j] & 255;
            int b3 = (int)sq[(ii * 4 + 3) * 36 + j] & 255;
            reinterpret_cast<int*>(g_qxt)[(n * P_ + p) * 24 + ii] =
                b0 | (b1 << 8) | (b2 << 16) | (b3 << 24);
        }
    }
}

// ---------------- kernel: conv1 via mma.sync (112 pix x 72 co, K=96) ----------------
// 224 threads / 7 warps (one per 16-pixel group), each m16 x n72 (9 nb), 3 k32 steps.
// 21 KB smem + 72 regs -> 4 blocks/SM.
__global__ __launch_bounds__(224, 4) void k_conv1m()
{
    __shared__ __align__(16) char smc[20608 + 576];
    int* sA = reinterpret_cast<int*>(smc);               // [112][28]
    int* sW = reinterpret_cast<int*>(smc + 12544);       // [72][28]
    int8_t* sS = reinterpret_cast<int8_t*>(smc);         // overlay after mma: [72][116]
    float* sAf = reinterpret_cast<float*>(smc + 20608);  // 72
    float* sBf = sAf + 72;

    int t = threadIdx.x, w = t >> 5, lane = t & 31;
    int q = lane >> 2, rr = lane & 3;
    int pix0 = blockIdx.x * 112;
    int co0  = blockIdx.y * 72;

    // load A: 672 int4
    {
        const int4* gA = reinterpret_cast<const int4*>(g_qxt + (size_t)pix0 * 96);
#pragma unroll
        for (int it = 0; it < 3; it++) {
            int i = t + it * 224;
            int r = i / 6, c = i % 6;
            *reinterpret_cast<int4*>(&sA[r * 28 + c * 4]) = gA[i];
        }
    }
    // load W: 432 int4
    {
        const int4* gW = reinterpret_cast<const int4*>(g_qw1 + (size_t)co0 * 96);
#pragma unroll
        for (int it = 0; it < 2; it++) {
            int i = t + it * 224;
            if (i < 432) {
                int r = i / 6, c = i % 6;
                *reinterpret_cast<int4*>(&sW[r * 28 + c * 4]) = gW[i];
            }
        }
    }
    if (t < 72) { sAf[t] = g_A1[co0 + t]; sBf[t] = g_B1[co0 + t]; }
    __syncthreads();

    int acc[9][4];
#pragma unroll
    for (int nb = 0; nb < 9; nb++)
#pragma unroll
        for (int j = 0; j < 4; j++) acc[nb][j] = 0;

    const int* ap = &sA[(w * 16 + q) * 28 + rr];
#pragma unroll
    for (int k = 0; k < 3; k++) {
        int a0 = ap[k * 8];
        int a1 = ap[k * 8 + 8 * 28];
        int a2 = ap[k * 8 + 4];
        int a3 = ap[k * 8 + 8 * 28 + 4];
#pragma unroll
        for (int nb = 0; nb < 9; nb++) {
            const int* bp = &sW[(nb * 8 + q) * 28 + rr + k * 8];
            mma8(acc[nb], a0, a1, a2, a3, bp[0], bp[4]);
        }
    }
    __syncthreads();   // all warps done reading sA/sW before overlay

    // stage quantized bytes [co][pix]
    float inv = g_c[0], cm = g_c[1];
    int pr0 = w * 16 + q, pr1 = pr0 + 8;
#pragma unroll
    for (int nb = 0; nb < 9; nb++) {
        int ca = nb * 8 + rr * 2, cb = ca + 1;
        sS[ca * 116 + pr0] = (int8_t)bnq(acc[nb][0], sAf[ca], sBf[ca], inv, cm);
        sS[cb * 116 + pr0] = (int8_t)bnq(acc[nb][1], sAf[cb], sBf[cb], inv, cm);
        sS[ca * 116 + pr1] = (int8_t)bnq(acc[nb][2], sAf[ca], sBf[ca], inv, cm);
        sS[cb * 116 + pr1] = (int8_t)bnq(acc[nb][3], sAf[cb], sBf[cb], inv, cm);
    }
    __syncthreads();

    // coalesced copy to planar: 72 co x 4 rows x 7 ints = 2016 ints
    int n = pix0 / P_;
    int yy = (pix0 % P_) / W_;
#pragma unroll
    for (int it = 0; it < 9; it++) {
        int i = t + it * 224;
        int co = i / 28, rem = i % 28, seg = rem / 7, wd = rem % 7;
        int val = *reinterpret_cast<const int*>(&sS[co * 116 + seg * 28 + wd * 4]);
        *reinterpret_cast<int*>(
            &g_q1p[(size_t)(co0 + co) * 30720 + n * 960 + (yy + seg + 1) * 32 + wd * 4]) = val;
    }
}

// ---------------- kernel: depthwise 3x3 + bn2 + relu6 + quant ----------------
__global__ __launch_bounds__(288) void k_dw()
{
    __shared__ __align__(16) int s_in[72 * 52];
    __shared__ __align__(16) int s_out[2016];
    int t  = threadIdx.x;
    int b  = blockIdx.x;
    int cg = b & 7;
    int s  = (b >> 3) % 7;
    int n  = b / 56;
    int c0 = cg * 72;

    const int4* g4 = reinterpret_cast<const int4*>(g_q1p);
    int4* s4 = reinterpret_cast<int4*>(s_in);
#pragma unroll
    for (int it = 0; it < 3; it++) {
        int idx = t + it * 288;
        int c = idx / 12, r4 = idx % 12;
        s4[c * 13 + r4] = g4[((c0 + c) * 32 + n) * 60 + s * 8 + r4];
    }
    __syncthreads();

    int c = t % 72, y = t / 72;
    int gc = c0 + c;
    int w0 = g_qw2r[gc * 4 + 0];
    int w1 = g_qw2r[gc * 4 + 1];
    int w2 = g_qw2r[gc * 4 + 2];
    float A = g_A2[gc], Bv = g_B2[gc];
    float inv = g_c[2], cm = g_c[3];

    const int4* sb = s4 + c * 13 + y * 2;
    int4 t0 = sb[0], t1 = sb[1], t2 = sb[2], t3 = sb[3], t4 = sb[4], t5 = sb[5];
    int r0[8] = {t0.x, t0.y, t0.z, t0.w, t1.x, t1.y, t1.z, t1.w};
    int r1[8] = {t2.x, t2.y, t2.z, t2.w, t3.x, t3.y, t3.z, t3.w};
    int r2[8] = {t4.x, t4.y, t4.z, t4.w, t5.x, t5.y, t5.z, t5.w};

    int8_t* so = reinterpret_cast<int8_t*>(s_out);
#pragma unroll
    for (int j = 0; j < 7; j++) {
        int p0 = j ? r0[j - 1] : 0, m0 = r0[j], q0 = r0[j + 1];
        int p1 = j ? r1[j - 1] : 0, m1 = r1[j], q1 = r1[j + 1];
        int p2 = j ? r2[j - 1] : 0, m2 = r2[j], q2 = r2[j + 1];
        int a0 = 0, a1 = 0, a2 = 0, a3 = 0;
        a0 = dpw(p0, m0, 0x5543, w0, a0);
        a1 = dpw(p0, m0, 0x6654, w0, a1);
        a2 = dpw(p0, m0, 0x7765, w0, a2);
        a3 = dpw(m0, q0, 0x4432, w0, a3);
        a0 = dpw(p1, m1, 0x5543, w1, a0);
        a1 = dpw(p1, m1, 0x6654, w1, a1);
        a2 = dpw(p1, m1, 0x7765, w1, a2);
        a3 = dpw(m1, q1, 0x4432, w1, a3);
        a0 = dpw(p2, m2, 0x5543, w2, a0);
        a1 = dpw(p2, m2, 0x6654, w2, a1);
        a2 = dpw(p2, m2, 0x7765, w2, a2);
        a3 = dpw(m2, q2, 0x4432, w2, a3);

        int pixb = (y * 28 + j * 4) * 72 + c;
        so[pixb      ] = (int8_t)bnq(a0, A, Bv, inv, cm);
        so[pixb + 72 ] = (int8_t)bnq(a1, A, Bv, inv, cm);
        so[pixb + 144] = (int8_t)bnq(a2, A, Bv, inv, cm);
        so[pixb + 216] = (int8_t)bnq(a3, A, Bv, inv, cm);
    }
    __syncthreads();

    int pbase = n * P_ + s * 112;
    int* gq2 = reinterpret_cast<int*>(g_q2);
#pragma unroll
    for (int it = 0; it < 7; it++) {
        int idx = t + it * 288;
        int pix = idx / 18, k = idx % 18;
        gq2[(pbase + pix) * 144 + cg * 18 + k] = s_out[idx];
    }
}

// ---------------- kernel: conv3 via mma.sync + cp.async double buffer ----------------
// 112 pix x 48 co, K=576 in 6 chunks of 96; 7 warps each m16 x n48.
// smem 36 KB -> 4 blocks/SM; grid 448 fits in ONE wave (4 x 148 = 592).
#define C3A(buf) ((buf) * 3136)
#define C3W(buf) (6272 + (buf) * 1344)
#define C3_SMEM (35840 + 384)

__global__ __launch_bounds__(224, 4) void k_conv3m(const float* __restrict__ x,
                                                   float* __restrict__ out)
{
    extern __shared__ __align__(16) int sU[];
    uint32_t sb = smem_u32(sU);
    float* sAf = reinterpret_cast<float*>(sU + 8960);
    float* sBf = sAf + 48;
    float* stg = reinterpret_cast<float*>(sU);   // overlay after final mma

    int t = threadIdx.x, w = t >> 5, lane = t & 31;
    int q = lane >> 2, rr = lane & 3;
    int pix0 = blockIdx.x * 112;
    int co0  = blockIdx.y * 48;

    if (t < 48) { sAf[t] = g_A3[co0 + t]; sBf[t] = g_B3[co0 + t]; }

    auto load_chunk = [&](int buf, int ch) {
        uint32_t ab = sb + C3A(buf) * 4;
        uint32_t wb = sb + C3W(buf) * 4;
#pragma unroll
        for (int it = 0; it < 3; it++) {
            int i = t + it * 224;                 // 672 int4
            int r = i / 6, c = i % 6;
            cpa16(ab + (uint32_t)(r * 28 + c * 4) * 4,
                  g_q2 + (size_t)(pix0 + r) * HID_ + ch * 96 + c * 16);
        }
#pragma unroll
        for (int it = 0; it < 2; it++) {
            int i = t + it * 224;                 // 288 int4
            if (i < 288) {
                int r = i / 6, c = i % 6;
                cpa16(wb + (uint32_t)(r * 28 + c * 4) * 4,
                      g_qw3 + (size_t)(co0 + r) * HID_ + ch * 96 + c * 16);
            }
        }
    };

    load_chunk(0, 0);
    CPCOMMIT();
    CPWAIT0();
    __syncthreads();

    int acc[6][4];
#pragma unroll
    for (int nb = 0; nb < 6; nb++)
#pragma unroll
        for (int j = 0; j < 4; j++) acc[nb][j] = 0;

#pragma unroll
    for (int ch = 0; ch < 6; ch++) {
        if (ch < 5) { load_chunk((ch + 1) & 1, ch + 1); CPCOMMIT(); }

        const int* sA = sU + C3A(ch & 1);
        const int* sW = sU + C3W(ch & 1);
        const int* ap = &sA[(w * 16 + q) * 28 + rr];
#pragma unroll
        for (int k = 0; k < 3; k++) {
            int a0 = ap[k * 8];
            int a1 = ap[k * 8 + 8 * 28];
            int a2 = ap[k * 8 + 4];
            int a3 = ap[k * 8 + 8 * 28 + 4];
#pragma unroll
            for (int nb = 0; nb < 6; nb++) {
                const int* bp = &sW[(nb * 8 + q) * 28 + rr + k * 8];
                mma8(acc[nb], a0, a1, a2, a3, bp[0], bp[4]);
            }
        }
        if (ch < 5) { CPWAIT0(); __syncthreads(); }
    }
    __syncthreads();   // all warps done before stage overlay

    // stage fp32 [co][pix] stride 113
    int pr0 = w * 16 + q, pr1 = pr0 + 8;
#pragma unroll
    for (int nb = 0; nb < 6; nb++) {
        int ca = nb * 8 + rr * 2, cb = ca + 1;
        stg[ca * 113 + pr0] = (float)acc[nb][0];
        stg[cb * 113 + pr0] = (float)acc[nb][1];
        stg[ca * 113 + pr1] = (float)acc[nb][2];
        stg[cb * 113 + pr1] = (float)acc[nb][3];
    }
    __syncthreads();

    int n = pix0 / P_;
    int prow = pix0 % P_;
#pragma unroll
    for (int it = 0; it < 24; it++) {
        int i = t + it * 224;
        int co = i / 112, p = i % 112;
        int off = (n * C_ + co0 + co) * P_ + prow + p;
        out[off] = x[off] + fmaf(stg[co * 113 + p], sAf[co], sBf[co]);
    }
}

// ---------------- launch ----------------
extern "C" void kernel_launch(void* const* d_in, const int* in_sizes, int n_in,
                              void* d_out, int out_size)
{
    const float* x   = (const float*)d_in[0];
    const float* w1  = (const float*)d_in[1];
    const float* w2  = (const float*)d_in[2];
    const float* w3  = (const float*)d_in[3];
    const float* aw1 = (const float*)d_in[4];
    const float* ax1 = (const float*)d_in[5];
    const float* g1  = (const float*)d_in[6];
    const float* b1  = (const float*)d_in[7];
    const float* m1  = (const float*)d_in[8];
    const float* v1  = (const float*)d_in[9];
    const float* aw2 = (const float*)d_in[10];
    const float* ax2 = (const float*)d_in[11];
    const float* g2  = (const float*)d_in[12];
    const float* b2  = (const float*)d_in[13];
    const float* m2  = (const float*)d_in[14];
    const float* v2  = (const float*)d_in[15];
    const float* aw3 = (const float*)d_in[16];
    const float* ax3 = (const float*)d_in[17];
    const float* g3  = (const float*)d_in[18];
    const float* b3  = (const float*)d_in[19];
    const float* m3  = (const float*)d_in[20];
    const float* v3  = (const float*)d_in[21];
    float* out = (float*)d_out;

    cudaFuncSetAttribute(k_conv3m, cudaFuncAttributeMaxDynamicSharedMemorySize, C3_SMEM);

    k_setup<<<72, 256>>>(w1, w2, w3, aw1, ax1, g1, b1, m1, v1,
                         aw2, ax2, g2, b2, m2, v2, aw3, ax3, g3, b3, m3, v3);
    k_quantx<<<B_ * 25, 256>>>(x, ax1);
    k_conv1m<<<dim3(NP_ / 112, 8), 224>>>();
    k_dw<<<1792, 288>>>();
    k_conv3m<<<dim3(NP_ / 112, 2), 224, C3_SMEM>>>(x, out);
}

// round 10
// speedup vs baseline: 1.3264x; 1.0255x over previous
#include <cuda_runtime.h>
#include <cuda_bf16.h>
#include <cstdint>

// Problem constants
#define B_   32
#define C_   96
#define HID_ 576
#define H_   28
#define W_   28
#define P_   784
#define NP_  25088

// ---------------- device scratch ----------------
__device__ __align__(16) int8_t g_qxt[NP_ * C_];              // [pix][96] int8
__device__ __align__(16) int8_t g_q1p[HID_ * B_ * 30 * 32];   // planar halo layout
__device__ __align__(16) int8_t g_q2 [NP_ * HID_];            // [pix][576] int8
__device__ __align__(16) int8_t g_qw1[HID_ * C_];             // [co][96]
__device__ __align__(16) int8_t g_qw3[C_ * HID_];             // [co][576]
__device__ __align__(16) int    g_qw2r[HID_ * 4];
__device__ __align__(16) float  g_A1[HID_], g_B1[HID_];       // folded with 1/ax2
__device__ __align__(16) float  g_A2[HID_], g_B2[HID_];       // folded with 1/ax3
__device__ __align__(16) float  g_A3[C_],   g_B3[C_];
__device__ float g_c[4];   // [1]=min(6/ax2,7)  [3]=min(6/ax3,7)

// ---------------- helpers ----------------
__device__ __forceinline__ void mma8(int* c, int a0, int a1, int a2, int a3,
                                     int b0, int b1) {
    asm volatile("mma.sync.aligned.m16n8k32.row.col.s32.s8.s8.s32 "
        "{%0,%1,%2,%3}, {%4,%5,%6,%7}, {%8,%9}, {%0,%1,%2,%3};"
        : "+r"(c[0]), "+r"(c[1]), "+r"(c[2]), "+r"(c[3])
        : "r"(a0), "r"(a1), "r"(a2), "r"(a3), "r"(b0), "r"(b1));
}
__device__ __forceinline__ uint32_t smem_u32(const void* p) {
    uint32_t a;
    asm("{ .reg .u64 t; cvta.to.shared.u64 t, %1; cvt.u32.u64 %0, t; }" : "=r"(a) : "l"(p));
    return a;
}
__device__ __forceinline__ void cpa16(uint32_t s, const void* g) {
    asm volatile("cp.async.cg.shared.global [%0], [%1], 16;" :: "r"(s), "l"(g));
}
#define CPCOMMIT() asm volatile("cp.async.commit_group;" ::: "memory")
#define CPWAIT0()  asm volatile("cp.async.wait_group 0;" ::: "memory")

__device__ __forceinline__ int dpw(int lo, int hi, int sel, int w, int acc) {
    return __dp4a((int)__byte_perm((unsigned)lo, (unsigned)hi, (unsigned)sel), w, acc);
}
// folded epilogue: rint(clamp(acc*A + B, 0, cm))
__device__ __forceinline__ int bnq(int acc, float A, float Bv, float cm) {
    float f = fmaf((float)acc, A, Bv);
    f = fminf(fmaxf(f, 0.0f), cm);
    return (int)rintf(f);
}

// ---------------- kernel: prep = setup + halo zero + quantize/transpose x ----------------
// grid 800 x 256: quantx part per-block; setup part strided across all threads.
__global__ void k_prep(const float* __restrict__ x,
                       const float* w1, const float* w2, const float* w3,
                       const float* aw1, const float* ax1,
                       const float* g1, const float* b1, const float* m1, const float* v1,
                       const float* aw2, const float* ax2,
                       const float* g2, const float* b2, const float* m2, const float* v2,
                       const float* aw3, const float* ax3,
                       const float* g3, const float* b3, const float* m3, const float* v3)
{
    __shared__ int8_t sq[C_ * 36];
    int t   = threadIdx.x;
    int tid = blockIdx.x * 256 + t;
    int nt  = gridDim.x * 256;                 // 204800
    float a1 = aw1[0], a2 = aw2[0], a3 = aw3[0];

    // ---- setup (strided; most threads do <=1 element) ----
    if (tid < HID_ * B_) {                     // halo zero of g_q1p
        int4* p4 = reinterpret_cast<int4*>(g_q1p + (size_t)tid * 960);
        int4 z = make_int4(0, 0, 0, 0);
        p4[0] = z; p4[1] = z;
        p4[58] = z; p4[59] = z;
        int* pi = reinterpret_cast<int*>(g_q1p + (size_t)tid * 960);
#pragma unroll
        for (int r = 1; r < 29; r++) pi[r * 8 + 7] = 0;
    }
    for (int i = tid; i < HID_ * C_; i += nt)
        g_qw1[i] = (int8_t)(int)rintf(fminf(fmaxf(w1[i] / a1, -8.0f), 7.0f));
    for (int i = tid; i < C_ * HID_; i += nt)
        g_qw3[i] = (int8_t)(int)rintf(fminf(fmaxf(w3[i] / a3, -8.0f), 7.0f));
    for (int c = tid; c < HID_; c += nt) {
        int q[9];
#pragma unroll
        for (int tp = 0; tp < 9; tp++)
            q[tp] = (int)rintf(fminf(fmaxf(w2[c * 9 + tp] / a2, -8.0f), 7.0f));
#pragma unroll
        for (int r = 0; r < 3; r++)
            g_qw2r[c * 4 + r] = (q[3*r] & 255) | ((q[3*r+1] & 255) << 8) | ((q[3*r+2] & 255) << 16);
        float r2 = 1.0f / ax2[0];
        float r3 = 1.0f / ax3[0];
        float s1 = g1[c] / sqrtf(v1[c] + 1e-5f);
        g_A1[c] = ax1[0] * a1 * s1 * r2;                // folded with 1/ax2
        g_B1[c] = (b1[c] - m1[c] * s1) * r2;
        float s2 = g2[c] / sqrtf(v2[c] + 1e-5f);
        g_A2[c] = ax2[0] * a2 * s2 * r3;                // folded with 1/ax3
        g_B2[c] = (b2[c] - m2[c] * s2) * r3;
    }
    for (int c = tid; c < C_; c += nt) {
        float s3 = g3[c] / sqrtf(v3[c] + 1e-5f);
        g_A3[c] = ax3[0] * a3 * s3;
        g_B3[c] = b3[c] - m3[c] * s3;
    }
    if (tid == 0) {
        g_c[1] = fminf(6.0f / ax2[0], 7.0f);
        g_c[3] = fminf(6.0f / ax3[0], 7.0f);
    }

    // ---- quantize + transpose x (per block: 32 pixels of one image) ----
    int n  = blockIdx.x / 25;
    int p0 = (blockIdx.x % 25) * 32;
    float rax = 1.0f / ax1[0];                 // one div per thread, 12 elems each
#pragma unroll
    for (int r = 0; r < 12; r++) {
        int idx = t + r * 256;
        int c = idx >> 5, j = idx & 31;
        int p = p0 + j;
        float val = (p < P_) ? x[(n * C_ + c) * P_ + p] : 0.0f;
        float q = rintf(fminf(fmaxf(val * rax, -8.0f), 7.0f));
        sq[c * 36 + j] = (int8_t)(int)q;
    }
    __syncthreads();
#pragma unroll
    for (int r = 0; r < 3; r++) {
        int idx = t + r * 256;
        int j = idx / 24, ii = idx % 24;
        int p = p0 + j;
        if (p < P_) {
            int b0 = (int)sq[(ii * 4 + 0) * 36 + j] & 255;
            int b1v = (int)sq[(ii * 4 + 1) * 36 + j] & 255;
            int b2v = (int)sq[(ii * 4 + 2) * 36 + j] & 255;
            int b3v = (int)sq[(ii * 4 + 3) * 36 + j] & 255;
            reinterpret_cast<int*>(g_qxt)[(n * P_ + p) * 24 + ii] =
                b0 | (b1v << 8) | (b2v << 16) | (b3v << 24);
        }
    }
}

// ---------------- kernel: conv1 via mma.sync, single wave, 4 pix-tiles/block ----------------
// grid (56, 8): block = 72 co x 4x112 pix; 224 threads / 7 warps; A double-buffered cp.async.
// smem ints: A0 @0 (3136), A1 @3136, W @6272 (2016), stage @8288 (2088), floats @10376 (144)
#define C1A(buf) ((buf) * 3136)
#define C1W      6272
#define C1STG    8288
#define C1FLT    10376
__global__ __launch_bounds__(224, 4) void k_conv1m()
{
    __shared__ __align__(16) int sU[10520];    // 42080 bytes
    uint32_t sb = smem_u32(sU);
    int8_t* sS = reinterpret_cast<int8_t*>(sU + C1STG);
    float* sAf = reinterpret_cast<float*>(sU + C1FLT);
    float* sBf = sAf + 72;

    int t = threadIdx.x, w = t >> 5, lane = t & 31;
    int q = lane >> 2, rr = lane & 3;
    int tile0 = blockIdx.x * 4;
    int co0   = blockIdx.y * 72;

    // W once (432 int4) + A tile0 (672 int4), all async
    {
#pragma unroll
        for (int it = 0; it < 2; it++) {
            int i = t + it * 224;
            if (i < 432) {
                int r = i / 6, c = i % 6;
                cpa16(sb + (uint32_t)(C1W + r * 28 + c * 4) * 4,
                      g_qw1 + (size_t)(co0 + r) * 96 + c * 16);
            }
        }
#pragma unroll
        for (int it = 0; it < 3; it++) {
            int i = t + it * 224;
            int r = i / 6, c = i % 6;
            cpa16(sb + (uint32_t)(C1A(0) + r * 28 + c * 4) * 4,
                  g_qxt + (size_t)(tile0 * 112 + r) * 96 + c * 16);
        }
        CPCOMMIT();
    }
    if (t < 72) { sAf[t] = g_A1[co0 + t]; sBf[t] = g_B1[co0 + t]; }
    float cm = g_c[1];
    CPWAIT0();
    __syncthreads();

#pragma unroll
    for (int tl = 0; tl < 4; tl++) {
        int buf = tl & 1;
        if (tl < 3) {      // prefetch next A into other buffer
#pragma unroll
            for (int it = 0; it < 3; it++) {
                int i = t + it * 224;
                int r = i / 6, c = i % 6;
                cpa16(sb + (uint32_t)(C1A(buf ^ 1) + r * 28 + c * 4) * 4,
                      g_qxt + (size_t)((tile0 + tl + 1) * 112 + r) * 96 + c * 16);
            }
            CPCOMMIT();
        }

        int acc[9][4];
#pragma unroll
        for (int nb = 0; nb < 9; nb++)
#pragma unroll
            for (int j = 0; j < 4; j++) acc[nb][j] = 0;

        const int* ap = sU + C1A(buf) + (w * 16 + q) * 28 + rr;
#pragma unroll
        for (int k = 0; k < 3; k++) {
            int a0 = ap[k * 8];
            int a1 = ap[k * 8 + 8 * 28];
            int a2 = ap[k * 8 + 4];
            int a3 = ap[k * 8 + 8 * 28 + 4];
#pragma unroll
            for (int nb = 0; nb < 9; nb++) {
                const int* bp = sU + C1W + (nb * 8 + q) * 28 + rr + k * 8;
                mma8(acc[nb], a0, a1, a2, a3, bp[0], bp[4]);
            }
        }

        // stage quantized bytes [co][pix] (separate region — no overlay hazard)
        int pr0 = w * 16 + q, pr1 = pr0 + 8;
#pragma unroll
        for (int nb = 0; nb < 9; nb++) {
            int ca = nb * 8 + rr * 2, cb = ca + 1;
            sS[ca * 116 + pr0] = (int8_t)bnq(acc[nb][0], sAf[ca], sBf[ca], cm);
            sS[cb * 116 + pr0] = (int8_t)bnq(acc[nb][1], sAf[cb], sBf[cb], cm);
            sS[ca * 116 + pr1] = (int8_t)bnq(acc[nb][2], sAf[ca], sBf[ca], cm);
            sS[cb * 116 + pr1] = (int8_t)bnq(acc[nb][3], sAf[cb], sBf[cb], cm);
        }
        __syncthreads();

        // coalesced planar store: 72 co x 4 rows x 7 ints = 2016 ints
        int pix0 = (tile0 + tl) * 112;
        int n = pix0 / P_;
        int yy = (pix0 % P_) / W_;
#pragma unroll
        for (int it = 0; it < 9; it++) {
            int i = t + it * 224;
            int co = i / 28, rem = i % 28, seg = rem / 7, wd = rem % 7;
            int val = *reinterpret_cast<const int*>(&sS[co * 116 + seg * 28 + wd * 4]);
            *reinterpret_cast<int*>(
                &g_q1p[(size_t)(co0 + co) * 30720 + n * 960 + (yy + seg + 1) * 32 + wd * 4]) = val;
        }
        if (tl < 3) CPWAIT0();
        __syncthreads();    // stage reuse + A[buf] reuse guard
    }
}

// ---------------- kernel: depthwise 3x3 + bn2 + relu6 + quant ----------------
__global__ __launch_bounds__(288) void k_dw()
{
    __shared__ __align__(16) int s_in[72 * 52];
    __shared__ __align__(16) int s_out[2016];
    int t  = threadIdx.x;
    int b  = blockIdx.x;
    int cg = b & 7;
    int s  = (b >> 3) % 7;
    int n  = b / 56;
    int c0 = cg * 72;

    const int4* g4 = reinterpret_cast<const int4*>(g_q1p);
    int4* s4 = reinterpret_cast<int4*>(s_in);
#pragma unroll
    for (int it = 0; it < 3; it++) {
        int idx = t + it * 288;
        int c = idx / 12, r4 = idx % 12;
        s4[c * 13 + r4] = g4[((c0 + c) * 32 + n) * 60 + s * 8 + r4];
    }
    __syncthreads();

    int c = t % 72, y = t / 72;
    int gc = c0 + c;
    int w0 = g_qw2r[gc * 4 + 0];
    int w1 = g_qw2r[gc * 4 + 1];
    int w2 = g_qw2r[gc * 4 + 2];
    float A = g_A2[gc], Bv = g_B2[gc];
    float cm = g_c[3];

    const int4* sb = s4 + c * 13 + y * 2;
    int4 t0 = sb[0], t1 = sb[1], t2 = sb[2], t3 = sb[3], t4 = sb[4], t5 = sb[5];
    int r0[8] = {t0.x, t0.y, t0.z, t0.w, t1.x, t1.y, t1.z, t1.w};
    int r1[8] = {t2.x, t2.y, t2.z, t2.w, t3.x, t3.y, t3.z, t3.w};
    int r2[8] = {t4.x, t4.y, t4.z, t4.w, t5.x, t5.y, t5.z, t5.w};

    int8_t* so = reinterpret_cast<int8_t*>(s_out);
#pragma unroll
    for (int j = 0; j < 7; j++) {
        int p0 = j ? r0[j - 1] : 0, m0 = r0[j], q0 = r0[j + 1];
        int p1 = j ? r1[j - 1] : 0, m1 = r1[j], q1 = r1[j + 1];
        int p2 = j ? r2[j - 1] : 0, m2 = r2[j], q2 = r2[j + 1];
        int a0 = 0, a1 = 0, a2 = 0, a3 = 0;
        a0 = dpw(p0, m0, 0x5543, w0, a0);
        a1 = dpw(p0, m0, 0x6654, w0, a1);
        a2 = dpw(p0, m0, 0x7765, w0, a2);
        a3 = dpw(m0, q0, 0x4432, w0, a3);
        a0 = dpw(p1, m1, 0x5543, w1, a0);
        a1 = dpw(p1, m1, 0x6654, w1, a1);
        a2 = dpw(p1, m1, 0x7765, w1, a2);
        a3 = dpw(m1, q1, 0x4432, w1, a3);
        a0 = dpw(p2, m2, 0x5543, w2, a0);
        a1 = dpw(p2, m2, 0x6654, w2, a1);
        a2 = dpw(p2, m2, 0x7765, w2, a2);
        a3 = dpw(m2, q2, 0x4432, w2, a3);

        int pixb = (y * 28 + j * 4) * 72 + c;
        so[pixb      ] = (int8_t)bnq(a0, A, Bv, cm);
        so[pixb + 72 ] = (int8_t)bnq(a1, A, Bv, cm);
        so[pixb + 144] = (int8_t)bnq(a2, A, Bv, cm);
        so[pixb + 216] = (int8_t)bnq(a3, A, Bv, cm);
    }
    __syncthreads();

    int pbase = n * P_ + s * 112;
    int* gq2 = reinterpret_cast<int*>(g_q2);
#pragma unroll
    for (int it = 0; it < 7; it++) {
        int idx = t + it * 288;
        int pix = idx / 18, k = idx % 18;
        gq2[(pbase + pix) * 144 + cg * 18 + k] = s_out[idx];
    }
}

// ---------------- kernel: conv3 via mma.sync + cp.async double buffer ----------------
// 112 pix x 48 co, K=576 in 6 chunks of 96; 7 warps each m16 x n48; 4 blocks/SM, 1 wave.
#define C3A(buf) ((buf) * 3136)
#define C3W(buf) (6272 + (buf) * 1344)
#define C3_SMEM (35840 + 384)

__global__ __launch_bounds__(224, 4) void k_conv3m(const float* __restrict__ x,
                                                   float* __restrict__ out)
{
    extern __shared__ __align__(16) int sU[];
    uint32_t sb = smem_u32(sU);
    float* sAf = reinterpret_cast<float*>(sU + 8960);
    float* sBf = sAf + 48;
    float* stg = reinterpret_cast<float*>(sU);   // overlay after final mma

    int t = threadIdx.x, w = t >> 5, lane = t & 31;
    int q = lane >> 2, rr = lane & 3;
    int pix0 = blockIdx.x * 112;
    int co0  = blockIdx.y * 48;

    if (t < 48) { sAf[t] = g_A3[co0 + t]; sBf[t] = g_B3[co0 + t]; }

    auto load_chunk = [&](int buf, int ch) {
        uint32_t ab = sb + C3A(buf) * 4;
        uint32_t wb = sb + C3W(buf) * 4;
#pragma unroll
        for (int it = 0; it < 3; it++) {
            int i = t + it * 224;
            int r = i / 6, c = i % 6;
            cpa16(ab + (uint32_t)(r * 28 + c * 4) * 4,
                  g_q2 + (size_t)(pix0 + r) * HID_ + ch * 96 + c * 16);
        }
#pragma unroll
        for (int it = 0; it < 2; it++) {
            int i = t + it * 224;
            if (i < 288) {
                int r = i / 6, c = i % 6;
                cpa16(wb + (uint32_t)(r * 28 + c * 4) * 4,
                      g_qw3 + (size_t)(co0 + r) * HID_ + ch * 96 + c * 16);
            }
        }
    };

    load_chunk(0, 0);
    CPCOMMIT();
    CPWAIT0();
    __syncthreads();

    int acc[6][4];
#pragma unroll
    for (int nb = 0; nb < 6; nb++)
#pragma unroll
        for (int j = 0; j < 4; j++) acc[nb][j] = 0;

#pragma unroll
    for (int ch = 0; ch < 6; ch++) {
        if (ch < 5) { load_chunk((ch + 1) & 1, ch + 1); CPCOMMIT(); }

        const int* sA = sU + C3A(ch & 1);
        const int* sW = sU + C3W(ch & 1);
        const int* ap = &sA[(w * 16 + q) * 28 + rr];
#pragma unroll
        for (int k = 0; k < 3; k++) {
            int a0 = ap[k * 8];
            int a1 = ap[k * 8 + 8 * 28];
            int a2 = ap[k * 8 + 4];
            int a3 = ap[k * 8 + 8 * 28 + 4];
#pragma unroll
            for (int nb = 0; nb < 6; nb++) {
                const int* bp = &sW[(nb * 8 + q) * 28 + rr + k * 8];
                mma8(acc[nb], a0, a1, a2, a3, bp[0], bp[4]);
            }
        }
        if (ch < 5) { CPWAIT0(); __syncthreads(); }
    }
    __syncthreads();

    int pr0 = w * 16 + q, pr1 = pr0 + 8;
#pragma unroll
    for (int nb = 0; nb < 6; nb++) {
        int ca = nb * 8 + rr * 2, cb = ca + 1;
        stg[ca * 113 + pr0] = (float)acc[nb][0];
        stg[cb * 113 + pr0] = (float)acc[nb][1];
        stg[ca * 113 + pr1] = (float)acc[nb][2];
        stg[cb * 113 + pr1] = (float)acc[nb][3];
    }
    __syncthreads();

    int n = pix0 / P_;
    int prow = pix0 % P_;
#pragma unroll
    for (int it = 0; it < 24; it++) {
        int i = t + it * 224;
        int co = i / 112, p = i % 112;
        int off = (n * C_ + co0 + co) * P_ + prow + p;
        out[off] = x[off] + fmaf(stg[co * 113 + p], sAf[co], sBf[co]);
    }
}

// ---------------- launch ----------------
extern "C" void kernel_launch(void* const* d_in, const int* in_sizes, int n_in,
                              void* d_out, int out_size)
{
    const float* x   = (const float*)d_in[0];
    const float* w1  = (const float*)d_in[1];
    const float* w2  = (const float*)d_in[2];
    const float* w3  = (const float*)d_in[3];
    const float* aw1 = (const float*)d_in[4];
    const float* ax1 = (const float*)d_in[5];
    const float* g1  = (const float*)d_in[6];
    const float* b1  = (const float*)d_in[7];
    const float* m1  = (const float*)d_in[8];
    const float* v1  = (const float*)d_in[9];
    const float* aw2 = (const float*)d_in[10];
    const float* ax2 = (const float*)d_in[11];
    const float* g2  = (const float*)d_in[12];
    const float* b2  = (const float*)d_in[13];
    const float* m2  = (const float*)d_in[14];
    const float* v2  = (const float*)d_in[15];
    const float* aw3 = (const float*)d_in[16];
    const float* ax3 = (const float*)d_in[17];
    const float* g3  = (const float*)d_in[18];
    const float* b3  = (const float*)d_in[19];
    const float* m3  = (const float*)d_in[20];
    const float* v3  = (const float*)d_in[21];
    float* out = (float*)d_out;

    cudaFuncSetAttribute(k_conv3m, cudaFuncAttributeMaxDynamicSharedMemorySize, C3_SMEM);

    k_prep<<<B_ * 25, 256>>>(x, w1, w2, w3, aw1, ax1, g1, b1, m1, v1,
                             aw2, ax2, g2, b2, m2, v2, aw3, ax3, g3, b3, m3, v3);
    k_conv1m<<<dim3(56, 8), 224>>>();
    k_dw<<<1792, 288>>>();
    k_conv3m<<<dim3(NP_ / 112, 2), 224, C3_SMEM>>>(x, out);
}